// round 6
// baseline (speedup 1.0000x reference)
#include <cuda_runtime.h>
#include <cuda_bf16.h>

typedef unsigned int u32;

__device__ __forceinline__ float tanh_fast(float x) {
    float y;
    asm("tanh.approx.f32 %0, %1;" : "=f"(y) : "f"(x));
    return y;
}
// Pack two f32 into bf16x2: {hi16 = cvt(hi), lo16 = cvt(lo)}.
__device__ __forceinline__ u32 pk2(float hi, float lo) {
    u32 d;
    asm("cvt.rn.bf16x2.f32 %0, %1, %2;" : "=r"(d) : "f"(hi), "f"(lo));
    return d;
}
// bf16 halves of a packed reg, as f32 (bf16 = high 16 bits of f32).
__device__ __forceinline__ float lo_f(u32 p) { return __uint_as_float(p << 16); }
__device__ __forceinline__ float hi_f(u32 p) { return __uint_as_float(p & 0xFFFF0000u); }

__device__ __forceinline__ void mma16816(float d[4],
    u32 a0, u32 a1, u32 a2, u32 a3, u32 b0, u32 b1,
    float c0, float c1, float c2, float c3)
{
    asm("mma.sync.aligned.m16n8k16.row.col.f32.bf16.bf16.f32 "
        "{%0,%1,%2,%3}, {%4,%5,%6,%7}, {%8,%9}, {%10,%11,%12,%13};"
        : "=f"(d[0]), "=f"(d[1]), "=f"(d[2]), "=f"(d[3])
        : "r"(a0), "r"(a1), "r"(a2), "r"(a3), "r"(b0), "r"(b1),
          "f"(c0), "f"(c1), "f"(c2), "f"(c3));
}

// 3-term split matvec: D = (Ahi@Bhi + bias) + Ahi@Blo + Alo@Bhi.
// A_lo is consumed last so its (longer) production path has slack.
__device__ __forceinline__ void mma3(float d[4],
    u32 ah0, u32 ah1, u32 ah2, u32 ah3,
    u32 al0, u32 al1, u32 al2, u32 al3,
    const u32 bh[2], const u32 bl[2], const float bc[2])
{
    mma16816(d, ah0, ah1, ah2, ah3, bh[0], bh[1], bc[0], bc[1], bc[0], bc[1]);
    mma16816(d, ah0, ah1, ah2, ah3, bl[0], bl[1], d[0], d[1], d[2], d[3]);
    mma16816(d, al0, al1, al2, al3, bh[0], bh[1], d[0], d[1], d[2], d[3]);
}

// Systolic 4-layer tanh RNN on tensor cores. One warp = 16 batch rows, all 4
// layers; layer l at step i computes timestep t = i - l from step i-1 outputs.
//
// m16n8k16 alignment: D[16,8] lane layout (rows g,g+8; cols 2c,2c+1) is
// IDENTICAL to the A fragment's own-h half (regs 0,1) and to the input half
// (regs 2,3) of the NEXT layer — so tanh(D), packed to bf16x2, feeds both with
// no shuffles. Precision: h and W are split hi+lo in bf16 (3 mma terms, fp32
// accumulate, lo*lo dropped ~1e-5). x enters only layer 0's k=8 column; lanes
// with c!=0 hold zero weights there, so no predication is needed.
//
// UPD guarded by HEADN (layers 0..HEADN-1 update) for the 4 head steps where
// t<0 lanes must hold h0.
#define UPD(L, D, HEADN)                                                      \
    do { if ((L) < (HEADN)) {                                                 \
        const float t0 = tanh_fast((D)[0]);                                   \
        const float t1 = tanh_fast((D)[1]);                                   \
        const float t2 = tanh_fast((D)[2]);                                   \
        const float t3 = tanh_fast((D)[3]);                                   \
        const u32 n0 = pk2(t1, t0), n1 = pk2(t3, t2);                         \
        hl[L][0] = pk2(t1 - hi_f(n0), t0 - lo_f(n0));                         \
        hl[L][1] = pk2(t3 - hi_f(n1), t2 - lo_f(n1));                         \
        hh[L][0] = n0; hh[L][1] = n1;                                         \
    } } while (0)

#define STEP(IVAL, U, HEADN, PFG)                                             \
    do {                                                                      \
        const int i_ = (IVAL);                                                \
        const float xa = __shfl_sync(0xffffffffu, xr[U], grp);                \
        const float xb = __shfl_sync(0xffffffffu, xr[U], grp + 8);            \
        const u32 xh0 = pk2(0.f, xa);                                         \
        const u32 xh1 = pk2(0.f, xb);                                         \
        const u32 xl0 = pk2(0.f, xa - lo_f(xh0));                             \
        const u32 xl1 = pk2(0.f, xb - lo_f(xh1));                             \
        float d0[4], d1[4], d2[4], d3[4];                                     \
        /* all mmas read OLD hh/hl; updates happen after */                   \
        mma3(d0, hh[0][0], hh[0][1], xh0,      xh1,                           \
                 hl[0][0], hl[0][1], xl0,      xl1,                           \
                 bhi[0], blo[0], biasc[0]);                                   \
        mma3(d1, hh[1][0], hh[1][1], hh[0][0], hh[0][1],                      \
                 hl[1][0], hl[1][1], hl[0][0], hl[0][1],                      \
                 bhi[1], blo[1], biasc[1]);                                   \
        mma3(d2, hh[2][0], hh[2][1], hh[1][0], hh[1][1],                      \
                 hl[2][0], hl[2][1], hl[1][0], hl[1][1],                      \
                 bhi[2], blo[2], biasc[2]);                                   \
        mma3(d3, hh[3][0], hh[3][1], hh[2][0], hh[2][1],                      \
                 hl[3][0], hl[3][1], hl[2][0], hl[2][1],                      \
                 bhi[3], blo[3], biasc[3]);                                   \
        UPD(0, d0, HEADN); UPD(1, d1, HEADN);                                 \
        UPD(2, d2, HEADN); UPD(3, d3, HEADN);                                 \
        if (PFG) xr[U] = ((i_ + 4) < T) ? __ldg(xp) : 0.0f;                   \
        else     xr[U] = __ldg(xp);                                           \
        xp += B;                                                              \
    } while (0)

__global__ void __launch_bounds__(64, 1) rnnmma_kernel(
    const float* __restrict__ x,        // [T, B]
    const float* __restrict__ h0,       // [4, B, 8]
    const float* __restrict__ W_ih0,    // [8, 1]
    const float* __restrict__ W_ih_rest,// [3, 8, 8]
    const float* __restrict__ W_hh,     // [4, 8, 8]
    const float* __restrict__ b_ih,     // [4, 8]
    const float* __restrict__ b_hh,     // [4, 8]
    const float* __restrict__ W_out,    // [1, 8]
    const float* __restrict__ b_out,    // [1]
    float* __restrict__ out,            // [B]
    int T, int B)
{
    const int warp = threadIdx.x >> 5;
    const int lane = threadIdx.x & 31;
    const int b0   = (blockIdx.x * 2 + warp) * 16;   // 16 batch rows per warp
    if (b0 >= B) return;
    const int grp = lane >> 2;   // fragment row group (0..7)
    const int c   = lane & 3;    // thread-in-group (0..3)
    const int j0  = 2 * c;       // output-unit column base

    // B fragments (col-major k x n=8): lane holds B[k = j0, j0+1][n = grp]
    // (Wh part) and B[k = j0+8, j0+9][n = grp] (Wi part). Split hi/lo bf16.
    u32 bhi[4][2], blo[4][2];
    float biasc[4][2];
    #pragma unroll
    for (int l = 0; l < 4; ++l) {
        const float w0 = W_hh[(l * 8 + grp) * 8 + j0];
        const float w1 = W_hh[(l * 8 + grp) * 8 + j0 + 1];
        float v0, v1;
        if (l == 0) { v0 = (c == 0) ? W_ih0[grp] : 0.0f; v1 = 0.0f; }
        else {
            v0 = W_ih_rest[((l - 1) * 8 + grp) * 8 + j0];
            v1 = W_ih_rest[((l - 1) * 8 + grp) * 8 + j0 + 1];
        }
        const float w0h = __bfloat162float(__float2bfloat16(w0));
        const float w1h = __bfloat162float(__float2bfloat16(w1));
        const float v0h = __bfloat162float(__float2bfloat16(v0));
        const float v1h = __bfloat162float(__float2bfloat16(v1));
        bhi[l][0] = pk2(w1h, w0h);
        bhi[l][1] = pk2(v1h, v0h);
        blo[l][0] = pk2(w1 - w1h, w0 - w0h);
        blo[l][1] = pk2(v1 - v1h, v0 - v0h);
        biasc[l][0] = b_ih[l * 8 + j0] + b_hh[l * 8 + j0];
        biasc[l][1] = b_ih[l * 8 + j0 + 1] + b_hh[l * 8 + j0 + 1];
    }

    // h state as A-fragment regs (hi + lo bf16x2), rows grp and grp+8.
    u32 hh[4][2], hl[4][2];
    #pragma unroll
    for (int l = 0; l < 4; ++l) {
        const float a0 = h0[((size_t)(l * B + b0 + grp)) * 8 + j0];
        const float a1 = h0[((size_t)(l * B + b0 + grp)) * 8 + j0 + 1];
        const float a2 = h0[((size_t)(l * B + b0 + grp + 8)) * 8 + j0];
        const float a3 = h0[((size_t)(l * B + b0 + grp + 8)) * 8 + j0 + 1];
        const u32 p0 = pk2(a1, a0), p1 = pk2(a3, a2);
        hh[l][0] = p0; hh[l][1] = p1;
        hl[l][0] = pk2(a1 - hi_f(p0), a0 - lo_f(p0));
        hl[l][1] = pk2(a3 - hi_f(p1), a2 - lo_f(p1));
    }

    // x prefetch ring: lanes 0..15 carry batch rows 0..15 (16..31 duplicate).
    const int xlane = lane & 15;
    float xr[4];
    #pragma unroll
    for (int p = 0; p < 4; ++p)
        xr[p] = (p < T) ? x[(size_t)p * B + b0 + xlane] : 0.0f;
    const float* xp = x + (size_t)4 * B + b0 + xlane;

    // Head: 4 steps; layer l starts updating at step l.
    STEP(0, 0, 1, true);
    STEP(1, 1, 2, true);
    STEP(2, 2, 3, true);
    STEP(3, 3, 4, true);

    // Main: unguarded prefetch (i+4 <= T-1 guaranteed by bound).
    const int main_end = (T - 4) & ~3;
    for (int io = 4; io < main_end; io += 4) {
        STEP(io + 0, 0, 4, false);
        STEP(io + 1, 1, 4, false);
        STEP(io + 2, 2, 4, false);
        STEP(io + 3, 3, 4, false);
    }

    // Epilogue: guarded prefetch; post-T layer 0-2 outputs are unused and
    // finite (tanh-bounded); layer 3's last update lands exactly at t = T-1.
    const int NITER = T + 3;
    for (int i = main_end; i < NITER; ++i)
        STEP(i, i & 3, 4, true);

    // Readout: layer 3 h(T-1). Lane holds units j0, j0+1 of rows grp, grp+8.
    {
        const float h00 = lo_f(hh[3][0]) + lo_f(hl[3][0]);
        const float h01 = hi_f(hh[3][0]) + hi_f(hl[3][0]);
        const float h10 = lo_f(hh[3][1]) + lo_f(hl[3][1]);
        const float h11 = hi_f(hh[3][1]) + hi_f(hl[3][1]);
        const float w0 = W_out[j0], w1 = W_out[j0 + 1];
        float pr0 = h00 * w0 + h01 * w1;
        float pr1 = h10 * w0 + h11 * w1;
        pr0 += __shfl_xor_sync(0xffffffffu, pr0, 1);
        pr0 += __shfl_xor_sync(0xffffffffu, pr0, 2);
        pr1 += __shfl_xor_sync(0xffffffffu, pr1, 1);
        pr1 += __shfl_xor_sync(0xffffffffu, pr1, 2);
        if (c == 0) {
            const float bo = b_out[0];
            out[b0 + grp]     = pr0 + bo;
            out[b0 + grp + 8] = pr1 + bo;
        }
    }
}

extern "C" void kernel_launch(void* const* d_in, const int* in_sizes, int n_in,
                              void* d_out, int out_size) {
    const float* x         = (const float*)d_in[0];
    const float* h0        = (const float*)d_in[1];
    const float* W_ih0     = (const float*)d_in[2];
    const float* W_ih_rest = (const float*)d_in[3];
    const float* W_hh      = (const float*)d_in[4];
    const float* b_ih      = (const float*)d_in[5];
    const float* b_hh      = (const float*)d_in[6];
    const float* W_out     = (const float*)d_in[7];
    const float* b_out     = (const float*)d_in[8];

    const int B = in_sizes[1] / 32;   // h0: [4, B, 8]
    const int T = in_sizes[0] / B;    // x:  [T, B, 1]

    // One warp per 16 batch rows; block = 64 (2 warps -> SMSP 0,1 per SM).
    const int nwarps = (B + 15) / 16;
    const int grid   = (nwarps + 1) / 2;

    rnnmma_kernel<<<grid, 64>>>(x, h0, W_ih0, W_ih_rest, W_hh, b_ih, b_hh,
                                W_out, b_out, (float*)d_out, T, B);
}

// round 7
// speedup vs baseline: 1.3054x; 1.3054x over previous
#include <cuda_runtime.h>
#include <cuda_bf16.h>

typedef unsigned int u32;

__device__ __forceinline__ float tanh_fast(float x) {
    float y;
    asm("tanh.approx.f32 %0, %1;" : "=f"(y) : "f"(x));
    return y;
}
// Pack two f32 into bf16x2: {hi16 = cvt(hi), lo16 = cvt(lo)}.
__device__ __forceinline__ u32 pk2(float hi, float lo) {
    u32 d;
    asm("cvt.rn.bf16x2.f32 %0, %1, %2;" : "=r"(d) : "f"(hi), "f"(lo));
    return d;
}
// bf16 halves of a packed reg, as f32 (bf16 = high 16 bits of f32).
__device__ __forceinline__ float lo_f(u32 p) { return __uint_as_float(p << 16); }
__device__ __forceinline__ float hi_f(u32 p) { return __uint_as_float(p & 0xFFFF0000u); }

__device__ __forceinline__ void mma16816(float d[4],
    u32 a0, u32 a1, u32 a2, u32 a3, u32 b0, u32 b1,
    float c0, float c1, float c2, float c3)
{
    asm("mma.sync.aligned.m16n8k16.row.col.f32.bf16.bf16.f32 "
        "{%0,%1,%2,%3}, {%4,%5,%6,%7}, {%8,%9}, {%10,%11,%12,%13};"
        : "=f"(d[0]), "=f"(d[1]), "=f"(d[2]), "=f"(d[3])
        : "r"(a0), "r"(a1), "r"(a2), "r"(a3), "r"(b0), "r"(b1),
          "f"(c0), "f"(c1), "f"(c2), "f"(c3));
}

// Systolic 4-layer tanh RNN on tensor cores, 8 REAL batch rows per warp
// (fragment rows 8..15 duplicate rows 0..7; their D outputs are ignored, so
// only 8 tanh per warp-step and UPD touches only D regs 0,1).
//
// Per layer, 3-term bf16-split matvec restructured into PARALLEL terms:
//   main  = Ah @ Bhi + bias          (1 HMMA)
//   cross = Ah @ Blo ; += Al @ Bhi   (2 serial HMMA; Al needed only for #2)
//   d     = main + cross             (2 FADD)
// so the serial HMMA depth on the recurrence path is 2, and the lo-residual
// (longest to produce) feeds only the last HMMA. All MMAs read OLD state;
// updates happen after. rel_err of this scheme measured 8.3e-5 in R6.
//
// UPDL guarded by HEADN for the 4 head steps (t<0 lanes must keep h0).
#define UPDL(L, DM, DC, HEADN)                                                \
    do { if ((L) < (HEADN)) {                                                 \
        const float z0 = (DM)[0] + (DC)[0];                                   \
        const float z1 = (DM)[1] + (DC)[1];                                   \
        const float t0 = tanh_fast(z0);                                       \
        const float t1 = tanh_fast(z1);                                       \
        const u32 n0 = pk2(t1, t0);                                           \
        hl[L] = pk2(t1 - hi_f(n0), t0 - lo_f(n0));                            \
        hh[L] = n0;                                                           \
    } } while (0)

#define STEP(IVAL, U, HEADN, PFG)                                             \
    do {                                                                      \
        const int i_ = (IVAL);                                                \
        const float xa = __shfl_sync(0xffffffffu, xr[U], grp);                \
        const u32 xh = pk2(0.f, xa);                                          \
        const u32 xl = pk2(0.f, xa - lo_f(xh));                               \
        float m0[4], m1[4], m2[4], m3[4];                                     \
        float c0[4], c1[4], c2[4], c3[4];                                     \
        /* main terms: Ah @ Bhi + bias (independent across layers) */         \
        mma16816(m0, hh[0], hh[0], xh,    xh,    bhi[0][0], bhi[0][1],        \
                 biasc[0][0], biasc[0][1], biasc[0][0], biasc[0][1]);         \
        mma16816(m1, hh[1], hh[1], hh[0], hh[0], bhi[1][0], bhi[1][1],        \
                 biasc[1][0], biasc[1][1], biasc[1][0], biasc[1][1]);         \
        mma16816(m2, hh[2], hh[2], hh[1], hh[1], bhi[2][0], bhi[2][1],        \
                 biasc[2][0], biasc[2][1], biasc[2][0], biasc[2][1]);         \
        mma16816(m3, hh[3], hh[3], hh[2], hh[2], bhi[3][0], bhi[3][1],        \
                 biasc[3][0], biasc[3][1], biasc[3][0], biasc[3][1]);         \
        /* cross term A: Ah @ Blo (zero C) */                                 \
        mma16816(c0, hh[0], hh[0], xh,    xh,    blo[0][0], blo[0][1],        \
                 0.f, 0.f, 0.f, 0.f);                                         \
        mma16816(c1, hh[1], hh[1], hh[0], hh[0], blo[1][0], blo[1][1],        \
                 0.f, 0.f, 0.f, 0.f);                                         \
        mma16816(c2, hh[2], hh[2], hh[1], hh[1], blo[2][0], blo[2][1],        \
                 0.f, 0.f, 0.f, 0.f);                                         \
        mma16816(c3, hh[3], hh[3], hh[2], hh[2], blo[3][0], blo[3][1],        \
                 0.f, 0.f, 0.f, 0.f);                                         \
        /* cross term B: Al @ Bhi, accumulated */                             \
        mma16816(c0, hl[0], hl[0], xl,    xl,    bhi[0][0], bhi[0][1],        \
                 c0[0], c0[1], c0[2], c0[3]);                                 \
        mma16816(c1, hl[1], hl[1], hl[0], hl[0], bhi[1][0], bhi[1][1],        \
                 c1[0], c1[1], c1[2], c1[3]);                                 \
        mma16816(c2, hl[2], hl[2], hl[1], hl[1], bhi[2][0], bhi[2][1],        \
                 c2[0], c2[1], c2[2], c2[3]);                                 \
        mma16816(c3, hl[3], hl[3], hl[2], hl[2], bhi[3][0], bhi[3][1],        \
                 c3[0], c3[1], c3[2], c3[3]);                                 \
        UPDL(0, m0, c0, HEADN);                                               \
        UPDL(1, m1, c1, HEADN);                                               \
        UPDL(2, m2, c2, HEADN);                                               \
        UPDL(3, m3, c3, HEADN);                                               \
        if (PFG) xr[U] = ((i_ + 4) < T) ? __ldg(xp) : 0.0f;                   \
        else     xr[U] = __ldg(xp);                                           \
        xp += B;                                                              \
    } while (0)

__global__ void __launch_bounds__(128, 1) rnnmma8_kernel(
    const float* __restrict__ x,        // [T, B]
    const float* __restrict__ h0,       // [4, B, 8]
    const float* __restrict__ W_ih0,    // [8, 1]
    const float* __restrict__ W_ih_rest,// [3, 8, 8]
    const float* __restrict__ W_hh,     // [4, 8, 8]
    const float* __restrict__ b_ih,     // [4, 8]
    const float* __restrict__ b_hh,     // [4, 8]
    const float* __restrict__ W_out,    // [1, 8]
    const float* __restrict__ b_out,    // [1]
    float* __restrict__ out,            // [B]
    int T, int B)
{
    const int warp = threadIdx.x >> 5;
    const int lane = threadIdx.x & 31;
    const int b0   = (blockIdx.x * 4 + warp) * 8;   // 8 real batch rows/warp
    if (b0 >= B) return;
    const int grp = lane >> 2;   // fragment row group (0..7) = real row
    const int c   = lane & 3;    // thread-in-group
    const int j0  = 2 * c;       // output-unit column base

    // B fragments (col-major k16 x n8): lane holds k = j0,j0+1 (Wh, k<8) and
    // k = 8+j0, 9+j0 (Wi) at column n = grp. Split hi/lo bf16.
    u32 bhi[4][2], blo[4][2];
    float biasc[4][2];
    #pragma unroll
    for (int l = 0; l < 4; ++l) {
        const float w0 = W_hh[(l * 8 + grp) * 8 + j0];
        const float w1 = W_hh[(l * 8 + grp) * 8 + j0 + 1];
        float v0, v1;
        if (l == 0) { v0 = (c == 0) ? W_ih0[grp] : 0.0f; v1 = 0.0f; }
        else {
            v0 = W_ih_rest[((l - 1) * 8 + grp) * 8 + j0];
            v1 = W_ih_rest[((l - 1) * 8 + grp) * 8 + j0 + 1];
        }
        const float w0h = __bfloat162float(__float2bfloat16(w0));
        const float w1h = __bfloat162float(__float2bfloat16(w1));
        const float v0h = __bfloat162float(__float2bfloat16(v0));
        const float v1h = __bfloat162float(__float2bfloat16(v1));
        bhi[l][0] = pk2(w1h, w0h);
        bhi[l][1] = pk2(v1h, v0h);
        blo[l][0] = pk2(w1 - w1h, w0 - w0h);
        blo[l][1] = pk2(v1 - v1h, v0 - v0h);
        biasc[l][0] = b_ih[l * 8 + j0] + b_hh[l * 8 + j0];
        biasc[l][1] = b_ih[l * 8 + j0 + 1] + b_hh[l * 8 + j0 + 1];
    }

    // h state: ONE hi + ONE lo bf16x2 per layer (units j0, j0+1 of row grp).
    u32 hh[4], hl[4];
    #pragma unroll
    for (int l = 0; l < 4; ++l) {
        const float a0 = h0[((size_t)(l * B + b0 + grp)) * 8 + j0];
        const float a1 = h0[((size_t)(l * B + b0 + grp)) * 8 + j0 + 1];
        const u32 p0 = pk2(a1, a0);
        hh[l] = p0;
        hl[l] = pk2(a1 - hi_f(p0), a0 - lo_f(p0));
    }

    // x prefetch ring: lanes 0..7 (and their aliases) carry rows 0..7.
    const int xlane = lane & 7;
    float xr[4];
    #pragma unroll
    for (int p = 0; p < 4; ++p)
        xr[p] = (p < T) ? x[(size_t)p * B + b0 + xlane] : 0.0f;
    const float* xp = x + (size_t)4 * B + b0 + xlane;

    // Head: 4 steps; layer l starts updating at step l.
    STEP(0, 0, 1, true);
    STEP(1, 1, 2, true);
    STEP(2, 2, 3, true);
    STEP(3, 3, 4, true);

    // Main: unguarded prefetch (i+4 <= T-1 guaranteed by bound).
    const int main_end = (T - 4) & ~3;
    for (int io = 4; io < main_end; io += 4) {
        STEP(io + 0, 0, 4, false);
        STEP(io + 1, 1, 4, false);
        STEP(io + 2, 2, 4, false);
        STEP(io + 3, 3, 4, false);
    }

    // Epilogue: guarded prefetch; post-T layer 0-2 outputs are unused and
    // finite; layer 3's last update lands exactly at t = T-1.
    const int NITER = T + 3;
    for (int i = main_end; i < NITER; ++i)
        STEP(i, i & 3, 4, true);

    // Readout: layer 3 h(T-1); lane holds units j0, j0+1 of row b0+grp.
    {
        const float h00 = lo_f(hh[3]) + lo_f(hl[3]);
        const float h01 = hi_f(hh[3]) + hi_f(hl[3]);
        float pr = h00 * W_out[j0] + h01 * W_out[j0 + 1];
        pr += __shfl_xor_sync(0xffffffffu, pr, 1);
        pr += __shfl_xor_sync(0xffffffffu, pr, 2);
        if (c == 0)
            out[b0 + grp] = pr + b_out[0];
    }
}

extern "C" void kernel_launch(void* const* d_in, const int* in_sizes, int n_in,
                              void* d_out, int out_size) {
    const float* x         = (const float*)d_in[0];
    const float* h0        = (const float*)d_in[1];
    const float* W_ih0     = (const float*)d_in[2];
    const float* W_ih_rest = (const float*)d_in[3];
    const float* W_hh      = (const float*)d_in[4];
    const float* b_ih      = (const float*)d_in[5];
    const float* b_hh      = (const float*)d_in[6];
    const float* W_out     = (const float*)d_in[7];
    const float* b_out     = (const float*)d_in[8];

    const int B = in_sizes[1] / 32;   // h0: [4, B, 8]
    const int T = in_sizes[0] / B;    // x:  [T, B, 1]

    // 8 real rows per warp -> B/8 warps; block 128 = 4 warps (one per SMSP).
    const int nwarps = (B + 7) / 8;
    const int grid   = (nwarps + 3) / 4;

    rnnmma8_kernel<<<grid, 128>>>(x, h0, W_ih0, W_ih_rest, W_hh, b_ih, b_hh,
                                  W_out, b_out, (float*)d_out, T, B);
}